// round 15
// baseline (speedup 1.0000x reference)
#include <cuda_runtime.h>
#include <stdint.h>

// RGBMem: inverted-index single-sweep, fully fused (2 launches).
//   logits[b,k] = dot(memory[row(b,k)], x[b]) / T,  row(b,0)=y[b], else idx[b,k]
//   labels = zeros
//   new_memory = memory with rows y[b] := normalize(0.5*memory[y]+0.5*x[b])
// Output (float32): [logits (bsz*Kp1)] [labels gap] [memory (n_data*128)]
// sweep: 2 rows/warp (16-lane halves), width-16 butterfly serves both rows.
// R15: sweep grid sized to EXACTLY one wave (sm_count * 8 blocks @ 32 regs)
// -- R14's 2048-block grid ran 1.68 waves, idling ~1/3 of the chip in wave 2.

#define T_INV (1.0f / 0.07f)
#define MAX_ROWS 524288
#define CAP 16

__device__ uint2 g_meta[MAX_ROWS];                   // .x=count, .y=upd flag
__device__ unsigned g_list[(size_t)MAX_ROWS * CAP];  // 32 MB scratch

__device__ __forceinline__ long long load_index(const void* p, unsigned i,
                                                int is64) {
    if (is64) return ((const long long*)p)[i];
    return (long long)((const int*)p)[i];
}

__device__ __forceinline__ int sniff_is64(const void* idx) {
    const unsigned* w = (const unsigned*)idx;
    int is64 = 1;
    #pragma unroll
    for (int i = 0; i < 16; i++)
        if (w[2 * i + 1] != 0u) { is64 = 0; break; }
    return is64;
}

// ---------------------------------------------------------------------------
// Build: inverted lists (entry = (b<<24)|i), update flags, labels zeroing.
// ---------------------------------------------------------------------------
__global__ void build_kernel(const float* __restrict__ x,
                             const void* __restrict__ y,
                             const void* __restrict__ idx,
                             const float* __restrict__ memory,
                             float* __restrict__ logits,
                             float* __restrict__ out_labels, int label_elems,
                             int bsz, unsigned Kp1, long long n_data) {
    __shared__ int s_is64;
    if (threadIdx.x == 0) s_is64 = sniff_is64(idx);
    __syncthreads();
    int is64 = s_is64;

    if (blockIdx.x == 0) {
        if (threadIdx.x < (unsigned)bsz) {
            long long r = load_index(y, threadIdx.x, is64);
            r = r < 0 ? 0 : (r >= n_data ? n_data - 1 : r);
            atomicMax(&g_meta[r].y, threadIdx.x + 1u);   // last-write-wins
        }
        for (int t = threadIdx.x; t < label_elems; t += blockDim.x)
            out_labels[t] = 0.0f;
    }

    unsigned total = (unsigned)bsz * Kp1;
    unsigned i = blockIdx.x * blockDim.x + threadIdx.x;
    unsigned stride = gridDim.x * blockDim.x;
    for (; i < total; i += stride) {
        unsigned b = i / Kp1;
        unsigned k = i - b * Kp1;
        long long row = (k == 0) ? load_index(y, b, is64)
                                 : load_index(idx, i, is64);
        row = row < 0 ? 0 : (row >= n_data ? n_data - 1 : row);
        unsigned p = atomicAdd(&g_meta[row].x, 1u);
        if (p < CAP) {
            g_list[(size_t)row * CAP + p] = (b << 24) | i;
        } else {
            // direct fallback (Poisson tail, ~never; keeps CAP safe)
            const float* mr = memory + row * 128;
            const float* xr = x + b * 128;
            float s = 0.0f;
            for (int d = 0; d < 128; d++) s += __ldg(mr + d) * __ldg(xr + d);
            logits[i] = s * T_INV;
        }
    }
}

// ---------------------------------------------------------------------------
// Sweep: 2 rows per warp, one per 16-lane half. Lane covers 8 floats of its
// row. Width-16 butterfly (4 steps) reduces both rows at once.
// ---------------------------------------------------------------------------
__global__ void __launch_bounds__(256, 8) sweep_kernel(
    const float* __restrict__ x,
    const float4* __restrict__ mem4,
    float4* __restrict__ out_mem4,
    float* __restrict__ logits,
    unsigned n_data) {
    __shared__ float4 xs[16 * 32];
    int tid = threadIdx.x;
    for (int i = tid; i < 16 * 32; i += blockDim.x)
        xs[i] = ((const float4*)x)[i];
    __syncthreads();

    unsigned lane = tid & 31u;
    unsigned half = lane >> 4;                    // which row of the pair
    unsigned hl = lane & 15u;                     // lane within half
    unsigned hmask = 0xFFFFu << (half * 16u);     // member mask of this half
    unsigned warp = ((unsigned)blockIdx.x * blockDim.x + tid) >> 5;
    unsigned nwarps = ((unsigned)gridDim.x * blockDim.x) >> 5;

    // per-thread xs base pointers (hoisted: b varies, hl fixed)
    const float4* xs0 = xs + hl;
    const float4* xs1 = xs + hl + 16u;

    for (unsigned rb = warp * 2u; rb < n_data; rb += nwarps * 2u) {
        unsigned r = rb + half;
        bool valid = r < n_data;
        unsigned rs = valid ? r : (n_data - 1u);

        // full 512B row per half: 2 float4 per lane (warp = 1KB contiguous)
        float4 m0 = __ldcs(mem4 + rs * 32u + hl);
        float4 m1 = __ldcs(mem4 + rs * 32u + hl + 16u);
        uint2 meta = g_meta[rs];
        unsigned c = valid ? (meta.x > CAP ? CAP : meta.x) : 0u;
        unsigned upd = valid ? meta.y : 0u;

        unsigned co = __shfl_xor_sync(0xffffffffu, c, 16);
        unsigned cmax = c > co ? c : co;          // warp-uniform

        const uint4* lst4 = (const uint4*)(g_list + (size_t)rs * CAP);
        for (unsigned base = 0; base < cmax; base += 4u) {
            uint4 L = lst4[base >> 2];            // 4 entries per LDG.128
            #pragma unroll
            for (int j = 0; j < 4; j++) {
                unsigned e = base + (unsigned)j;
                if (e >= cmax) break;             // warp-uniform exit
                bool act = e < c;
                unsigned ent = (j == 0) ? L.x : (j == 1) ? L.y
                             : (j == 2) ? L.z : L.w;
                unsigned b = (ent >> 24) & 15u;   // mask: garbage-safe
                unsigned i = ent & 0xFFFFFFu;
                float4 xv0 = xs0[b * 32u];
                float4 xv1 = xs1[b * 32u];
                float s = m0.x * xv0.x + m0.y * xv0.y + m0.z * xv0.z +
                          m0.w * xv0.w + m1.x * xv1.x + m1.y * xv1.y +
                          m1.z * xv1.z + m1.w * xv1.w;
                #pragma unroll
                for (int off = 8; off; off >>= 1)  // uniform: full mask OK
                    s += __shfl_xor_sync(0xffffffffu, s, off);
                if (act && hl == 0) __stcs(logits + i, s * T_INV);
            }
        }

        if (valid) {
            if (upd == 0) {
                float4* dst = out_mem4 + r * 32u;
                __stcs(dst + hl, m0);
                __stcs(dst + hl + 16u, m1);
            } else {
                // cold path, divergent within warp: per-half mask shuffles
                unsigned b = upd - 1u;
                float4 xv0 = xs0[b * 32u];
                float4 xv1 = xs1[b * 32u];
                float4 v0, v1;
                v0.x = 0.5f * (m0.x + xv0.x); v0.y = 0.5f * (m0.y + xv0.y);
                v0.z = 0.5f * (m0.z + xv0.z); v0.w = 0.5f * (m0.w + xv0.w);
                v1.x = 0.5f * (m1.x + xv1.x); v1.y = 0.5f * (m1.y + xv1.y);
                v1.z = 0.5f * (m1.z + xv1.z); v1.w = 0.5f * (m1.w + xv1.w);
                float s = v0.x * v0.x + v0.y * v0.y + v0.z * v0.z +
                          v0.w * v0.w + v1.x * v1.x + v1.y * v1.y +
                          v1.z * v1.z + v1.w * v1.w;
                #pragma unroll
                for (int off = 8; off; off >>= 1)
                    s += __shfl_xor_sync(hmask, s, off);
                float inv = 1.0f / fmaxf(sqrtf(s), 1e-12f);
                v0.x *= inv; v0.y *= inv; v0.z *= inv; v0.w *= inv;
                v1.x *= inv; v1.y *= inv; v1.z *= inv; v1.w *= inv;
                float4* dst = out_mem4 + r * 32u;
                __stcs(dst + hl, v0);
                __stcs(dst + hl + 16u, v1);
            }
            if (hl == 0) g_meta[r] = make_uint2(0u, 0u);  // self-clean
        }
    }
}

// ---------------------------------------------------------------------------
// Fallback path (shape out of range): R2-proven kernels.
// ---------------------------------------------------------------------------
__global__ void copy_mem_kernel(const float4* __restrict__ src,
                                float4* __restrict__ dst, long long n4) {
    long long i = (long long)blockIdx.x * blockDim.x + threadIdx.x;
    long long stride = (long long)gridDim.x * blockDim.x;
    for (; i < n4; i += stride) dst[i] = src[i];
}

__global__ void logits_kernel(const float* __restrict__ x,
                              const void* __restrict__ y,
                              const void* __restrict__ idx,
                              const float* __restrict__ memory,
                              float* __restrict__ logits,
                              int bsz, unsigned Kp1, long long n_data) {
    __shared__ float4 xs[16 * 32];
    __shared__ int s_is64;
    int tid = threadIdx.x;
    if (tid == 0) s_is64 = sniff_is64(idx);
    int nx4 = bsz * 32;
    for (int i = tid; i < nx4; i += blockDim.x) xs[i] = ((const float4*)x)[i];
    __syncthreads();
    int is64 = s_is64;

    int lane = tid & 31;
    unsigned warp = (blockIdx.x * blockDim.x + tid) >> 5;
    unsigned nwarps = (gridDim.x * blockDim.x) >> 5;
    unsigned total = (unsigned)bsz * Kp1;

    for (unsigned i = warp; i < total; i += nwarps) {
        unsigned b = i / Kp1;
        unsigned k = i - b * Kp1;
        long long row = (k == 0) ? load_index(y, b, is64)
                                 : load_index(idx, i, is64);
        row = row < 0 ? 0 : (row >= n_data ? n_data - 1 : row);
        float4 mm = __ldg((const float4*)(memory + row * 128) + lane);
        float4 xv = xs[b * 32 + lane];
        float s = mm.x * xv.x + mm.y * xv.y + mm.z * xv.z + mm.w * xv.w;
        #pragma unroll
        for (int off = 16; off; off >>= 1)
            s += __shfl_xor_sync(0xffffffffu, s, off);
        if (lane == 0) logits[i] = s * T_INV;
    }
}

__global__ void update_kernel(const float* __restrict__ x,
                              const void* __restrict__ y,
                              const void* __restrict__ idx,
                              const float* __restrict__ memory,
                              float* __restrict__ out_mem,
                              float* __restrict__ out_labels,
                              int label_elems, long long n_data) {
    int b = blockIdx.x;
    int t = threadIdx.x;
    __shared__ int s_is64;
    if (t == 0) s_is64 = sniff_is64(idx);
    __syncthreads();
    long long row = load_index(y, (unsigned)b, s_is64);
    row = row < 0 ? 0 : (row >= n_data ? n_data - 1 : row);

    float v = memory[row * 128 + t] * 0.5f + x[b * 128 + t] * 0.5f;
    float s = v * v;
    #pragma unroll
    for (int off = 16; off; off >>= 1)
        s += __shfl_xor_sync(0xffffffffu, s, off);
    __shared__ float ws[4];
    if ((t & 31) == 0) ws[t >> 5] = s;
    __syncthreads();
    float tot = ws[0] + ws[1] + ws[2] + ws[3];
    float denom = fmaxf(sqrtf(tot), 1e-12f);
    out_mem[row * 128 + t] = v / denom;
    if (b == 0 && t < label_elems) out_labels[t] = 0.0f;
}

// ---------------------------------------------------------------------------
extern "C" void kernel_launch(void* const* d_in, const int* in_sizes, int n_in,
                              void* d_out, int out_size) {
    const float* x      = (const float*)d_in[0];   // [bsz, 128]
    const void*  y      = d_in[1];                 // [bsz]
    const void*  idx    = d_in[2];                 // [bsz, K+1]
    const float* memory = (const float*)d_in[3];   // [n_data, 128]

    int bsz = in_sizes[1];
    unsigned Kp1 = (unsigned)(in_sizes[2] / bsz);
    long long mem_elems = (long long)in_sizes[3];
    long long n_data = mem_elems / 128;
    long long logits_elems = (long long)bsz * Kp1;

    float* out = (float*)d_out;
    long long mem_off = (long long)out_size - mem_elems;
    if (mem_off < logits_elems) mem_off = logits_elems;
    float* out_mem = out + mem_off;
    float* out_labels = out + logits_elems;
    int label_elems = (int)(mem_off - logits_elems);

    // one full wave at 8 blocks/SM (32 regs, 8KB smem per 256-thr block)
    int sms = 0;
    cudaDeviceGetAttribute(&sms, cudaDevAttrMultiProcessorCount, 0);
    if (sms <= 0) sms = 148;
    int sweep_blocks = sms * 8;

    if (n_data <= MAX_ROWS && bsz <= 16 && logits_elems < (1 << 24)) {
        unsigned total = (unsigned)logits_elems;
        build_kernel<<<(total + 255) / 256, 256>>>(x, y, idx, memory, out,
                                                   out_labels, label_elems,
                                                   bsz, Kp1, n_data);
        sweep_kernel<<<sweep_blocks, 256>>>(x, (const float4*)memory,
                                            (float4*)out_mem, out,
                                            (unsigned)n_data);
    } else {
        copy_mem_kernel<<<2048, 256>>>((const float4*)memory,
                                       (float4*)out_mem, mem_elems / 4);
        logits_kernel<<<1184, 256>>>(x, y, idx, memory, out,
                                     bsz, Kp1, n_data);
        update_kernel<<<bsz, 128>>>(x, y, idx, memory, out_mem, out_labels,
                                    label_elems, n_data);
    }
}